// round 1
// baseline (speedup 1.0000x reference)
#include <cuda_runtime.h>
#include <math.h>

// Problem constants (B=1)
#define N_TOK   4096
#define D_MODEL 768
#define H_HEADS 12
#define HDIM    64
#define QKV_N   (3 * D_MODEL)   // 2304
#define ATT_SCALE 0.125f        // 64^-0.5

// Scratch (static device globals: allowed, no runtime allocation)
__device__ float g_qkv[N_TOK * QKV_N];      // 37.7 MB  [n][3D]
__device__ float g_att[N_TOK * D_MODEL];    // 12.6 MB  [n][D]

// ---------------------------------------------------------------------------
// SGEMM: C[M,N] = A[M,K] @ B[K,N] (+ bias[N]), all row-major, fp32.
// BM=BN=128, BK=8, 256 threads, 8x8 micro-tile per thread, float4 I/O.
// Requires M%128==0, N%128==0, K%8==0 (true for all three calls).
// ---------------------------------------------------------------------------
template <bool HAS_BIAS>
__global__ __launch_bounds__(256)
void sgemm_kernel(const float* __restrict__ A, const float* __restrict__ B,
                  const float* __restrict__ bias, float* __restrict__ C,
                  int M, int N, int K)
{
    constexpr int BM = 128, BN = 128, BK = 8, TM = 8, TN = 8;
    __shared__ float As[BK][BM];   // transposed A tile
    __shared__ float Bs[BK][BN];

    const int tid = threadIdx.x;
    const int bx = blockIdx.x, by = blockIdx.y;

    const float* Ablk = A + (size_t)by * BM * K;
    const float* Bblk = B + (size_t)bx * BN;

    const int tx = tid & 15;    // 0..15
    const int ty = tid >> 4;    // 0..15

    // loader mapping
    const int aRow = tid >> 1;           // 0..127
    const int aCol = (tid & 1) * 4;      // 0 or 4
    const int bRow = tid >> 5;           // 0..7
    const int bCol = (tid & 31) * 4;     // 0..124

    float acc[TM][TN] = {};
    float ar[TM], br[TN];

    for (int kt = 0; kt < K; kt += BK) {
        float4 av = *(const float4*)(Ablk + (size_t)aRow * K + kt + aCol);
        As[aCol + 0][aRow] = av.x;
        As[aCol + 1][aRow] = av.y;
        As[aCol + 2][aRow] = av.z;
        As[aCol + 3][aRow] = av.w;
        *(float4*)(&Bs[bRow][bCol]) =
            *(const float4*)(Bblk + (size_t)(kt + bRow) * N + bCol);
        __syncthreads();

        #pragma unroll
        for (int k = 0; k < BK; k++) {
            #pragma unroll
            for (int i = 0; i < TM; i += 4) {
                float4 v = *(const float4*)(&As[k][ty * TM + i]);
                ar[i] = v.x; ar[i+1] = v.y; ar[i+2] = v.z; ar[i+3] = v.w;
            }
            #pragma unroll
            for (int j = 0; j < TN; j += 4) {
                float4 v = *(const float4*)(&Bs[k][tx * TN + j]);
                br[j] = v.x; br[j+1] = v.y; br[j+2] = v.z; br[j+3] = v.w;
            }
            #pragma unroll
            for (int i = 0; i < TM; i++)
                #pragma unroll
                for (int j = 0; j < TN; j++)
                    acc[i][j] += ar[i] * br[j];
        }
        __syncthreads();
    }

    #pragma unroll
    for (int i = 0; i < TM; i++) {
        const size_t row = (size_t)by * BM + ty * TM + i;
        #pragma unroll
        for (int j = 0; j < TN; j += 4) {
            const int col = bx * BN + tx * TN + j;
            float4 v;
            v.x = acc[i][j + 0];
            v.y = acc[i][j + 1];
            v.z = acc[i][j + 2];
            v.w = acc[i][j + 3];
            if (HAS_BIAS) {
                v.x += bias[col + 0];
                v.y += bias[col + 1];
                v.z += bias[col + 2];
                v.w += bias[col + 3];
            }
            *(float4*)(C + row * N + col) = v;
        }
    }
}

// ---------------------------------------------------------------------------
// Flash attention, fp32. One block = (head h, 64-query tile).
// 256 threads as a 16x16 grid; each thread owns a 4x4 tile of S and O.
// Online softmax with 16-lane shuffle reductions per row group.
// ---------------------------------------------------------------------------
__global__ __launch_bounds__(256)
void attn_kernel()
{
    const int qb = blockIdx.x;   // 0..63
    const int h  = blockIdx.y;   // 0..11

    __shared__ float Qs[HDIM][64];    // [d][q], pre-scaled by ATT_SCALE
    __shared__ float Ks[HDIM][64];    // [d][kcol]
    __shared__ float Vs[64][HDIM];    // [krow][d]
    __shared__ float Ps[64][68];      // [q][kcol], padded stride 68

    const int tid = threadIdx.x;
    const int tx = tid & 15;     // key / headdim column group
    const int ty = tid >> 4;     // query row group

    // --- load Q tile once: rows qb*64.. , cols h*64.. of the Q section ---
    {
        const int r  = tid >> 2;
        const int d0 = (tid & 3) * 16;
        const float* qrow = g_qkv + (size_t)(qb * 64 + r) * QKV_N + h * HDIM;
        #pragma unroll
        for (int i = 0; i < 16; i += 4) {
            float4 v = *(const float4*)(qrow + d0 + i);
            Qs[d0 + i + 0][r] = v.x * ATT_SCALE;
            Qs[d0 + i + 1][r] = v.y * ATT_SCALE;
            Qs[d0 + i + 2][r] = v.z * ATT_SCALE;
            Qs[d0 + i + 3][r] = v.w * ATT_SCALE;
        }
    }

    float o[4][4] = {};
    float m[4], l[4];
    #pragma unroll
    for (int i = 0; i < 4; i++) { m[i] = -1e30f; l[i] = 0.0f; }

    for (int kb = 0; kb < N_TOK / 64; kb++) {
        __syncthreads();   // prior iter's reads of Ks/Vs/Ps complete
        // --- load K (transposed) and V tiles ---
        {
            const int r  = tid >> 2;
            const int d0 = (tid & 3) * 16;
            const float* krow = g_qkv + (size_t)(kb * 64 + r) * QKV_N + D_MODEL + h * HDIM;
            const float* vrow = g_qkv + (size_t)(kb * 64 + r) * QKV_N + 2 * D_MODEL + h * HDIM;
            #pragma unroll
            for (int i = 0; i < 16; i += 4) {
                float4 kv = *(const float4*)(krow + d0 + i);
                Ks[d0 + i + 0][r] = kv.x;
                Ks[d0 + i + 1][r] = kv.y;
                Ks[d0 + i + 2][r] = kv.z;
                Ks[d0 + i + 3][r] = kv.w;
                *(float4*)(&Vs[r][d0 + i]) = *(const float4*)(vrow + d0 + i);
            }
        }
        __syncthreads();

        // --- S = (Q*scale) @ K^T, 4x4 per thread ---
        float s[4][4] = {};
        #pragma unroll
        for (int k = 0; k < HDIM; k++) {
            float4 qv = *(const float4*)(&Qs[k][4 * ty]);
            float4 kv = *(const float4*)(&Ks[k][4 * tx]);
            float qa[4] = {qv.x, qv.y, qv.z, qv.w};
            float ka[4] = {kv.x, kv.y, kv.z, kv.w};
            #pragma unroll
            for (int i = 0; i < 4; i++)
                #pragma unroll
                for (int j = 0; j < 4; j++)
                    s[i][j] += qa[i] * ka[j];
        }

        // --- online softmax (row groups of 16 lanes) ---
        #pragma unroll
        for (int i = 0; i < 4; i++) {
            float mx = fmaxf(fmaxf(s[i][0], s[i][1]), fmaxf(s[i][2], s[i][3]));
            #pragma unroll
            for (int off = 8; off >= 1; off >>= 1)
                mx = fmaxf(mx, __shfl_xor_sync(0xffffffffu, mx, off, 16));
            const float mnew = fmaxf(m[i], mx);
            const float corr = __expf(m[i] - mnew);
            float rs = 0.0f;
            #pragma unroll
            for (int j = 0; j < 4; j++) {
                s[i][j] = __expf(s[i][j] - mnew);
                rs += s[i][j];
            }
            #pragma unroll
            for (int off = 8; off >= 1; off >>= 1)
                rs += __shfl_xor_sync(0xffffffffu, rs, off, 16);
            l[i] = l[i] * corr + rs;
            m[i] = mnew;
            #pragma unroll
            for (int j = 0; j < 4; j++) o[i][j] *= corr;
        }

        // --- stage P ---
        #pragma unroll
        for (int i = 0; i < 4; i++)
            #pragma unroll
            for (int j = 0; j < 4; j++)
                Ps[4 * ty + i][4 * tx + j] = s[i][j];
        __syncthreads();

        // --- O += P @ V ---
        #pragma unroll
        for (int k = 0; k < 64; k++) {
            float4 vv = *(const float4*)(&Vs[k][4 * tx]);
            float va[4] = {vv.x, vv.y, vv.z, vv.w};
            float pa[4];
            #pragma unroll
            for (int i = 0; i < 4; i++) pa[i] = Ps[4 * ty + i][k];
            #pragma unroll
            for (int i = 0; i < 4; i++)
                #pragma unroll
                for (int j = 0; j < 4; j++)
                    o[i][j] += pa[i] * va[j];
        }
    }

    // --- epilogue: normalize, scatter back to [n][D] layout ---
    #pragma unroll
    for (int i = 0; i < 4; i++) {
        const float inv = 1.0f / l[i];
        const size_t r = (size_t)qb * 64 + 4 * ty + i;
        float4 v;
        v.x = o[i][0] * inv;
        v.y = o[i][1] * inv;
        v.z = o[i][2] * inv;
        v.w = o[i][3] * inv;
        *(float4*)(g_att + r * D_MODEL + h * HDIM + 4 * tx) = v;
    }
}

// ---------------------------------------------------------------------------
extern "C" void kernel_launch(void* const* d_in, const int* in_sizes, int n_in,
                              void* d_out, int out_size)
{
    const float* x     = (const float*)d_in[0];  // (1,4096,768)
    const float* W_qkv = (const float*)d_in[1];  // (768,2304)
    const float* W_out = (const float*)d_in[2];  // (768,768)
    const float* b_out = (const float*)d_in[3];  // (768,)
    float* out = (float*)d_out;                  // (1,4096,768)

    float* qkv = nullptr;
    float* att = nullptr;
    cudaGetSymbolAddress((void**)&qkv, g_qkv);
    cudaGetSymbolAddress((void**)&att, g_att);

    // 1) QKV projection: (4096,768) @ (768,2304) -> g_qkv
    {
        dim3 grid(QKV_N / 128, N_TOK / 128);
        sgemm_kernel<false><<<grid, 256>>>(x, W_qkv, nullptr, qkv,
                                           N_TOK, QKV_N, D_MODEL);
    }
    // 2) attention: g_qkv -> g_att
    {
        dim3 grid(N_TOK / 64, H_HEADS);
        attn_kernel<<<grid, 256>>>();
    }
    // 3) output projection: (4096,768) @ (768,768) + b -> out
    {
        dim3 grid(D_MODEL / 128, N_TOK / 128);
        sgemm_kernel<true><<<grid, 256>>>(att, W_out, b_out, out,
                                          N_TOK, D_MODEL, D_MODEL);
    }
}

// round 2
// speedup vs baseline: 1.8826x; 1.8826x over previous
#include <cuda_runtime.h>
#include <cuda_fp16.h>

// Problem constants (B=1)
#define N_TOK   4096
#define D_MODEL 768
#define H_HEADS 12
#define HDIM    64
#define QKV_N   2304          // 3*D
#define K3_PROJ 2304          // 3*768 expanded-K for projections
#define ATT_SCALE 0.125f

// ---------------- scratch (device globals; no runtime allocation) ----------
__device__ float  g_qkv[N_TOK * QKV_N];          // 37.7 MB fp32
__device__ float  g_att[N_TOK * D_MODEL];        // 12.6 MB fp32
__device__ __half g_xe   [N_TOK  * K3_PROJ];     // 18.9 MB
__device__ __half g_wqkve[QKV_N  * K3_PROJ];     // 10.6 MB
__device__ __half g_atte [N_TOK  * K3_PROJ];     // 18.9 MB
__device__ __half g_woute[D_MODEL* K3_PROJ];     //  3.5 MB

// ---------------- helpers ---------------------------------------------------
__device__ __forceinline__ void hsplit(float x, __half& h, __half& l) {
    h = __float2half_rn(x);
    l = __float2half_rn(x - __half2float(h));
}
__device__ __forceinline__ unsigned hpack(__half a, __half b) {
    __half2 h2 = __halves2half2(a, b);   // a = low
    return *reinterpret_cast<unsigned*>(&h2);
}
__device__ __forceinline__ void mma16816(float c[4], const unsigned a[4], const unsigned b[2]) {
    asm volatile(
        "mma.sync.aligned.m16n8k16.row.col.f32.f16.f16.f32 "
        "{%0,%1,%2,%3}, {%4,%5,%6,%7}, {%8,%9}, {%0,%1,%2,%3};\n"
        : "+f"(c[0]), "+f"(c[1]), "+f"(c[2]), "+f"(c[3])
        : "r"(a[0]), "r"(a[1]), "r"(a[2]), "r"(a[3]), "r"(b[0]), "r"(b[1]));
}

// ---------------- expansion kernels -----------------------------------------
// A-pattern: X[M][K] fp32 -> Xe[M][3K] fp16, triplet {hi,hi,lo} per element.
__global__ void expandA_kernel(const float* __restrict__ X, __half* __restrict__ Xe,
                               int M, int K)
{
    const int kq = K >> 2;
    int idx = blockIdx.x * blockDim.x + threadIdx.x;
    if (idx >= M * kq) return;
    int m = idx / kq;
    int k0 = (idx - m * kq) * 4;
    float4 v = *(const float4*)(X + (size_t)m * K + k0);
    __half h0,l0,h1,l1,h2,l2,h3,l3;
    hsplit(v.x,h0,l0); hsplit(v.y,h1,l1); hsplit(v.z,h2,l2); hsplit(v.w,h3,l3);
    unsigned* o = (unsigned*)(Xe + (size_t)m * 3 * K + 3 * k0);
    o[0]=hpack(h0,h0); o[1]=hpack(l0,h1); o[2]=hpack(h1,l1);
    o[3]=hpack(h2,h2); o[4]=hpack(l2,h3); o[5]=hpack(h3,l3);
}
// B-pattern + transpose: W[K][N] fp32 -> We[N][3K] fp16, triplet {hi,lo,hi}.
__global__ void expandBT_kernel(const float* __restrict__ W, __half* __restrict__ We,
                                int K, int N)
{
    int idx = blockIdx.x * blockDim.x + threadIdx.x;
    if (idx >= K * N) return;
    int k = idx / N, n = idx - k * N;
    float x = W[(size_t)k * N + n];
    __half h, l; hsplit(x, h, l);
    __half* o = We + (size_t)n * 3 * K + 3 * k;
    o[0] = h; o[1] = l; o[2] = h;
}

// ---------------- HGEMM: C[M][N] = Ae[M][K3] @ Be[N][K3]^T (+bias) ----------
// BM=BN=128, BK=64, 256 thr (8 warps 4x2), warp tile 32x64, mma m16n8k16.
template <bool HAS_BIAS>
__global__ __launch_bounds__(256)
void hgemm_kernel(const __half* __restrict__ A, const __half* __restrict__ Bt,
                  const float* __restrict__ bias, float* __restrict__ C,
                  int M, int N, int K3)
{
    constexpr int LDSH = 72;   // halfs per SMEM row (pad: 72*2B = 144B, 16B-aligned)
    __shared__ __align__(16) __half As[128 * LDSH];
    __shared__ __align__(16) __half Bs[128 * LDSH];

    const int tid = threadIdx.x, wid = tid >> 5, lane = tid & 31;
    const int g = lane >> 2, t = lane & 3;
    const int wm = wid & 3, wn = wid >> 2;
    const int m0 = blockIdx.y * 128, n0 = blockIdx.x * 128;
    const int NT = K3 >> 6;

    const __half* Ab = A  + (size_t)m0 * K3;
    const __half* Bb = Bt + (size_t)n0 * K3;

    const int ld_row = tid >> 3;        // 0..31 (i adds 32 each)
    const int ld_c16 = (tid & 7) * 8;   // half offset of 16B chunk

    uint4 ra[4], rb[4];
    // prologue: tile 0
    #pragma unroll
    for (int i = 0; i < 4; i++) {
        int row = ld_row + i * 32;
        ra[i] = *(const uint4*)(Ab + (size_t)row * K3 + ld_c16);
        rb[i] = *(const uint4*)(Bb + (size_t)row * K3 + ld_c16);
    }
    #pragma unroll
    for (int i = 0; i < 4; i++) {
        int row = ld_row + i * 32;
        *(uint4*)(As + row * LDSH + ld_c16) = ra[i];
        *(uint4*)(Bs + row * LDSH + ld_c16) = rb[i];
    }
    __syncthreads();

    float cf[2][8][4] = {};

    for (int kt = 0; kt < NT; kt++) {
        if (kt + 1 < NT) {
            #pragma unroll
            for (int i = 0; i < 4; i++) {
                int row = ld_row + i * 32;
                ra[i] = *(const uint4*)(Ab + (size_t)row * K3 + (kt + 1) * 64 + ld_c16);
                rb[i] = *(const uint4*)(Bb + (size_t)row * K3 + (kt + 1) * 64 + ld_c16);
            }
        }
        #pragma unroll
        for (int kk = 0; kk < 4; kk++) {
            unsigned af[2][4], bf[8][2];
            #pragma unroll
            for (int mi = 0; mi < 2; mi++) {
                const __half* ap = As + (wm * 32 + mi * 16 + g) * LDSH + kk * 16 + 2 * t;
                af[mi][0] = *(const unsigned*)(ap);
                af[mi][1] = *(const unsigned*)(ap + 8 * LDSH);
                af[mi][2] = *(const unsigned*)(ap + 8);
                af[mi][3] = *(const unsigned*)(ap + 8 * LDSH + 8);
            }
            #pragma unroll
            for (int ni = 0; ni < 8; ni++) {
                const __half* bp = Bs + (wn * 64 + ni * 8 + g) * LDSH + kk * 16 + 2 * t;
                bf[ni][0] = *(const unsigned*)(bp);
                bf[ni][1] = *(const unsigned*)(bp + 8);
            }
            #pragma unroll
            for (int mi = 0; mi < 2; mi++)
                #pragma unroll
                for (int ni = 0; ni < 8; ni++)
                    mma16816(cf[mi][ni], af[mi], bf[ni]);
        }
        __syncthreads();
        if (kt + 1 < NT) {
            #pragma unroll
            for (int i = 0; i < 4; i++) {
                int row = ld_row + i * 32;
                *(uint4*)(As + row * LDSH + ld_c16) = ra[i];
                *(uint4*)(Bs + row * LDSH + ld_c16) = rb[i];
            }
            __syncthreads();
        }
    }

    #pragma unroll
    for (int mi = 0; mi < 2; mi++) {
        const int r0 = m0 + wm * 32 + mi * 16 + g;
        #pragma unroll
        for (int ni = 0; ni < 8; ni++) {
            const int col = n0 + wn * 64 + ni * 8 + 2 * t;
            float bv0 = 0.f, bv1 = 0.f;
            if (HAS_BIAS) { bv0 = bias[col]; bv1 = bias[col + 1]; }
            *(float2*)(C + (size_t)r0 * N + col) =
                make_float2(cf[mi][ni][0] + bv0, cf[mi][ni][1] + bv1);
            *(float2*)(C + (size_t)(r0 + 8) * N + col) =
                make_float2(cf[mi][ni][2] + bv0, cf[mi][ni][3] + bv1);
        }
    }
}

// ---------------- Flash attention with fp16-split mma -----------------------
// Block = (128-query tile, head). 8 warps; warp w owns q-rows w*16..w*16+15.
// Bc = 64 keys / iter. Expanded K' = 192 for both S=QK^T and O=PV.
#define SQ 200   // SMEM row stride in halfs (200*2B = 400B ≡ 4 banks mod 32: conflict-free frags)

__global__ __launch_bounds__(256)
void attn_kernel()
{
    extern __shared__ __half sm[];
    __half* Qe = sm;                 // [128][SQ]  A-pattern, pre-scaled
    __half* Ke = Qe + 128 * SQ;      // [64][SQ]   B-pattern (per key row)
    __half* Ve = Ke + 64 * SQ;       // [64][SQ]   d-major: Ve[d][3j+r], B-pattern
    __half* Pe = Ve + 64 * SQ;       // [128][SQ]  A-pattern

    const int qb = blockIdx.x, h = blockIdx.y;
    const int tid = threadIdx.x, wid = tid >> 5, lane = tid & 31;
    const int g = lane >> 2, t = lane & 3;

    // ---- load + expand Q tile (once) ----
    {
        const int r  = tid >> 1;
        const int d0 = (tid & 1) * 32;
        const float* qrow = g_qkv + (size_t)(qb * 128 + r) * QKV_N + h * HDIM + d0;
        unsigned* dst = (unsigned*)(Qe + r * SQ + 3 * d0);
        #pragma unroll
        for (int i = 0; i < 8; i++) {
            float4 v = *(const float4*)(qrow + i * 4);
            __half h0,l0,h1,l1,h2,l2,h3,l3;
            hsplit(v.x * ATT_SCALE, h0,l0); hsplit(v.y * ATT_SCALE, h1,l1);
            hsplit(v.z * ATT_SCALE, h2,l2); hsplit(v.w * ATT_SCALE, h3,l3);
            dst[i*6+0]=hpack(h0,h0); dst[i*6+1]=hpack(l0,h1); dst[i*6+2]=hpack(h1,l1);
            dst[i*6+3]=hpack(h2,h2); dst[i*6+4]=hpack(l2,h3); dst[i*6+5]=hpack(h3,l3);
        }
    }

    float of[8][4] = {};
    float m0 = -1e30f, m1 = -1e30f, l0s = 0.f, l1s = 0.f;

    for (int kb = 0; kb < N_TOK / 64; kb++) {
        __syncthreads();   // Ke/Ve free (prior iter's mma done)
        // ---- load + expand K, V (64 keys) ----
        {
            const int r  = tid >> 2;          // key index 0..63
            const int d0 = (tid & 3) * 16;
            const float* krow = g_qkv + (size_t)(kb * 64 + r) * QKV_N + D_MODEL + h * HDIM + d0;
            const float* vrow = krow + D_MODEL;
            unsigned* kdst = (unsigned*)(Ke + r * SQ + 3 * d0);
            #pragma unroll
            for (int i = 0; i < 4; i++) {
                float4 kv = *(const float4*)(krow + i * 4);
                __half h0,l0,h1,l1,h2,l2,h3,l3;
                hsplit(kv.x,h0,l0); hsplit(kv.y,h1,l1); hsplit(kv.z,h2,l2); hsplit(kv.w,h3,l3);
                kdst[i*6+0]=hpack(h0,l0); kdst[i*6+1]=hpack(h0,h1); kdst[i*6+2]=hpack(l1,h1);
                kdst[i*6+3]=hpack(h2,l2); kdst[i*6+4]=hpack(h2,h3); kdst[i*6+5]=hpack(l3,h3);

                float4 vv = *(const float4*)(vrow + i * 4);
                float va[4] = {vv.x, vv.y, vv.z, vv.w};
                #pragma unroll
                for (int e = 0; e < 4; e++) {
                    __half hh, ll; hsplit(va[e], hh, ll);
                    __half* vp = Ve + (d0 + i * 4 + e) * SQ + 3 * r;
                    vp[0] = hh; vp[1] = ll; vp[2] = hh;
                }
            }
        }
        __syncthreads();

        // ---- S = Q @ K^T (K' = 192) ----
        float sf[8][4];
        #pragma unroll
        for (int n = 0; n < 8; n++)
            #pragma unroll
            for (int e = 0; e < 4; e++) sf[n][e] = 0.f;

        #pragma unroll
        for (int kk = 0; kk < 12; kk++) {
            unsigned af[4];
            const __half* ap = Qe + (wid * 16 + g) * SQ + kk * 16 + 2 * t;
            af[0] = *(const unsigned*)(ap);
            af[1] = *(const unsigned*)(ap + 8 * SQ);
            af[2] = *(const unsigned*)(ap + 8);
            af[3] = *(const unsigned*)(ap + 8 * SQ + 8);
            #pragma unroll
            for (int n = 0; n < 8; n++) {
                const __half* bp = Ke + (n * 8 + g) * SQ + kk * 16 + 2 * t;
                unsigned bf[2];
                bf[0] = *(const unsigned*)(bp);
                bf[1] = *(const unsigned*)(bp + 8);
                mma16816(sf[n], af, bf);
            }
        }

        // ---- online softmax ----
        float mx0 = -1e30f, mx1 = -1e30f;
        #pragma unroll
        for (int n = 0; n < 8; n++) {
            mx0 = fmaxf(mx0, fmaxf(sf[n][0], sf[n][1]));
            mx1 = fmaxf(mx1, fmaxf(sf[n][2], sf[n][3]));
        }
        mx0 = fmaxf(mx0, __shfl_xor_sync(0xffffffffu, mx0, 1));
        mx0 = fmaxf(mx0, __shfl_xor_sync(0xffffffffu, mx0, 2));
        mx1 = fmaxf(mx1, __shfl_xor_sync(0xffffffffu, mx1, 1));
        mx1 = fmaxf(mx1, __shfl_xor_sync(0xffffffffu, mx1, 2));

        const float mn0 = fmaxf(m0, mx0), mn1 = fmaxf(m1, mx1);
        const float cr0 = __expf(m0 - mn0), cr1 = __expf(m1 - mn1);
        float rs0 = 0.f, rs1 = 0.f;

        __half* prow0 = Pe + (wid * 16 + g) * SQ;
        __half* prow1 = prow0 + 8 * SQ;
        #pragma unroll
        for (int n = 0; n < 8; n++) {
            float p00 = __expf(sf[n][0] - mn0);
            float p01 = __expf(sf[n][1] - mn0);
            float p10 = __expf(sf[n][2] - mn1);
            float p11 = __expf(sf[n][3] - mn1);
            rs0 += p00 + p01;
            rs1 += p10 + p11;
            const int j0 = n * 8 + 2 * t;       // even -> 3*j0 even -> u32-aligned
            __half a0,b0,a1,b1;
            hsplit(p00, a0, b0); hsplit(p01, a1, b1);
            unsigned* w0 = (unsigned*)(prow0 + 3 * j0);
            w0[0] = hpack(a0, a0); w0[1] = hpack(b0, a1); w0[2] = hpack(a1, b1);
            hsplit(p10, a0, b0); hsplit(p11, a1, b1);
            unsigned* w1 = (unsigned*)(prow1 + 3 * j0);
            w1[0] = hpack(a0, a0); w1[1] = hpack(b0, a1); w1[2] = hpack(a1, b1);
        }
        rs0 += __shfl_xor_sync(0xffffffffu, rs0, 1);
        rs0 += __shfl_xor_sync(0xffffffffu, rs0, 2);
        rs1 += __shfl_xor_sync(0xffffffffu, rs1, 1);
        rs1 += __shfl_xor_sync(0xffffffffu, rs1, 2);

        l0s = l0s * cr0 + rs0;  m0 = mn0;
        l1s = l1s * cr1 + rs1;  m1 = mn1;
        #pragma unroll
        for (int n = 0; n < 8; n++) {
            of[n][0] *= cr0; of[n][1] *= cr0;
            of[n][2] *= cr1; of[n][3] *= cr1;
        }
        __syncwarp();   // Pe is warp-local: order STS before LDS

        // ---- O += P @ V (K' = 192) ----
        #pragma unroll
        for (int kk = 0; kk < 12; kk++) {
            unsigned af[4];
            const __half* ap = Pe + (wid * 16 + g) * SQ + kk * 16 + 2 * t;
            af[0] = *(const unsigned*)(ap);
            af[1] = *(const unsigned*)(ap + 8 * SQ);
            af[2] = *(const unsigned*)(ap + 8);
            af[3] = *(const unsigned*)(ap + 8 * SQ + 8);
            #pragma unroll
            for (int n = 0; n < 8; n++) {
                const __half* bp = Ve + (n * 8 + g) * SQ + kk * 16 + 2 * t;
                unsigned bf[2];
                bf[0] = *(const unsigned*)(bp);
                bf[1] = *(const unsigned*)(bp + 8);
                mma16816(of[n], af, bf);
            }
        }
    }

    // ---- epilogue ----
    const float inv0 = 1.0f / l0s, inv1 = 1.0f / l1s;
    const int q0 = qb * 128 + wid * 16 + g;
    #pragma unroll
    for (int n = 0; n < 8; n++) {
        const int col = h * HDIM + n * 8 + 2 * t;
        *(float2*)(g_att + (size_t)q0 * D_MODEL + col) =
            make_float2(of[n][0] * inv0, of[n][1] * inv0);
        *(float2*)(g_att + (size_t)(q0 + 8) * D_MODEL + col) =
            make_float2(of[n][2] * inv1, of[n][3] * inv1);
    }
}

// ---------------------------------------------------------------------------
extern "C" void kernel_launch(void* const* d_in, const int* in_sizes, int n_in,
                              void* d_out, int out_size)
{
    const float* x     = (const float*)d_in[0];
    const float* W_qkv = (const float*)d_in[1];
    const float* W_out = (const float*)d_in[2];
    const float* b_out = (const float*)d_in[3];
    float* out = (float*)d_out;

    float  *qkv, *att;
    __half *xe, *wqkve, *atte, *woute;
    cudaGetSymbolAddress((void**)&qkv,   g_qkv);
    cudaGetSymbolAddress((void**)&att,   g_att);
    cudaGetSymbolAddress((void**)&xe,    g_xe);
    cudaGetSymbolAddress((void**)&wqkve, g_wqkve);
    cudaGetSymbolAddress((void**)&atte,  g_atte);
    cudaGetSymbolAddress((void**)&woute, g_woute);

    const int ATTN_SMEM = (128 + 64 + 64 + 128) * SQ * 2;  // 153600 B
    cudaFuncSetAttribute(attn_kernel, cudaFuncAttributeMaxDynamicSharedMemorySize, ATTN_SMEM);

    // 1) expand x (A-pattern) and W_qkv (B-pattern, transposed)
    {
        int n = N_TOK * (D_MODEL / 4);
        expandA_kernel<<<(n + 255) / 256, 256>>>(x, xe, N_TOK, D_MODEL);
    }
    {
        int n = D_MODEL * QKV_N;
        expandBT_kernel<<<(n + 255) / 256, 256>>>(W_qkv, wqkve, D_MODEL, QKV_N);
    }
    // 2) QKV projection
    {
        dim3 grid(QKV_N / 128, N_TOK / 128);
        hgemm_kernel<false><<<grid, 256>>>(xe, wqkve, nullptr, qkv, N_TOK, QKV_N, K3_PROJ);
    }
    // 3) attention
    {
        dim3 grid(N_TOK / 128, H_HEADS);
        attn_kernel<<<grid, 256, ATTN_SMEM>>>();
    }
    // 4) expand att (A-pattern) and W_out (B-pattern, transposed)
    {
        int n = N_TOK * (D_MODEL / 4);
        expandA_kernel<<<(n + 255) / 256, 256>>>(att, atte, N_TOK, D_MODEL);
    }
    {
        int n = D_MODEL * D_MODEL;
        expandBT_kernel<<<(n + 255) / 256, 256>>>(W_out, woute, D_MODEL, D_MODEL);
    }
    // 5) output projection (+bias)
    {
        dim3 grid(D_MODEL / 128, N_TOK / 128);
        hgemm_kernel<true><<<grid, 256>>>(atte, woute, b_out, out, N_TOK, D_MODEL, K3_PROJ);
    }
}